// round 3
// baseline (speedup 1.0000x reference)
#include <cuda_runtime.h>
#include <math.h>
#include <float.h>

// Problem constants (fixed by setup_inputs)
#define BB 4
#define CC 256
#define MM 1024
#define NN 16384
#define HH 224
#define WW 224
#define HWH (HH*WW)
#define KPOOL 4
#define OH (HH/KPOOL)   // 56
#define OW (WW/KPOOL)   // 56

// Scratch (zero-initialized at module load; every launch restores zeros)
__device__ float g_feat[(size_t)BB * HWH * CC];  // [b][pixel][c]  ~205MB
__device__ float g_cnt[(size_t)BB * HWH];        // [b][pixel]
__device__ float g_xt[(size_t)BB * MM * CC];     // xyz_feats transposed: [b][m][c]

// ---------------------------------------------------------------------------
// Kernel 1: transpose xyz_feats [B][C][M] -> g_xt [B][M][C]
// ---------------------------------------------------------------------------
__global__ void k_transpose(const float* __restrict__ X) {
    __shared__ float tile[32][33];
    int b  = blockIdx.z;
    int m0 = blockIdx.x * 32;
    int c0 = blockIdx.y * 32;
    int tx = threadIdx.x, ty = threadIdx.y;  // block (32,8)
    #pragma unroll
    for (int k = 0; k < 32; k += 8)
        tile[ty + k][tx] = X[((size_t)b * CC + (c0 + ty + k)) * MM + (m0 + tx)];
    __syncthreads();
    #pragma unroll
    for (int k = 0; k < 32; k += 8)
        g_xt[((size_t)b * MM + (m0 + ty + k)) * CC + (c0 + tx)] = tile[tx][ty + k];
}

// Reference-matching norm: r(r(r(x^2)+r(y^2))+r(z^2)), no fma contraction.
__device__ __forceinline__ float norm3_ref(float x, float y, float z) {
    return __fadd_rn(__fadd_rn(__fmul_rn(x, x), __fmul_rn(y, y)), __fmul_rn(z, z));
}

// Projection row: NO-FMA ascending chain, mirroring an XLA elementwise loop:
//   r( r( r(k0*x) + r(k1*y) ) + r(k2*z) )
__device__ __forceinline__ float proj_row(float k0, float k1, float k2,
                                          float x, float y, float z) {
    return __fadd_rn(__fadd_rn(__fmul_rn(k0, x), __fmul_rn(k1, y)), __fmul_rn(k2, z));
}

// ---------------------------------------------------------------------------
// Kernel 2: per-point 3-NN + inverse-distance interp + scatter-add to pixels
// One warp per point. Centers cached in SMEM.
// ---------------------------------------------------------------------------
__global__ void __launch_bounds__(256) k_knn_scatter(
    const float* __restrict__ pts,   // [B][N][3]
    const float* __restrict__ ctr,   // [B][M][3]
    const float* __restrict__ Km)    // [3][3]
{
    __shared__ float scx[MM], scy[MM], scz[MM], scn[MM];
    int b   = blockIdx.y;
    int tid = threadIdx.x;
    int lane = tid & 31;

    for (int i = tid; i < MM; i += blockDim.x) {
        float x = ctr[((size_t)b * MM + i) * 3 + 0];
        float y = ctr[((size_t)b * MM + i) * 3 + 1];
        float z = ctr[((size_t)b * MM + i) * 3 + 2];
        scx[i] = x; scy[i] = y; scz[i] = z;
        scn[i] = norm3_ref(x, y, z);
    }
    __syncthreads();

    float K00 = Km[0], K01 = Km[1], K02 = Km[2];
    float K10 = Km[3], K11 = Km[4], K12 = Km[5];
    float K20 = Km[6], K21 = Km[7], K22 = Km[8];

    int warp   = blockIdx.x * (blockDim.x >> 5) + (tid >> 5);
    int nwarps = gridDim.x * (blockDim.x >> 5);

    for (int n = warp; n < NN; n += nwarps) {
        const float* p = &pts[((size_t)b * NN + n) * 3];
        float px = p[0], py = p[1], pz = p[2];
        float pn = norm3_ref(px, py, pz);

        // per-lane top-3 (smallest distances, earliest index wins ties)
        float d0 = FLT_MAX, d1 = FLT_MAX, d2 = FLT_MAX;
        int   i0 = -1, i1 = -1, i2 = -1;
        #pragma unroll 4
        for (int j = 0; j < MM / 32; j++) {
            int m = j * 32 + lane;
            // GEMM-style fma chain (matches Eigen/cuBLAS ascending-k):
            float dot = fmaf(pz, scz[m], fmaf(py, scy[m], __fmul_rn(px, scx[m])));
            // d = r( r(pn + cn) - 2*dot )   (2*dot is exact)
            float d = __fsub_rn(__fadd_rn(pn, scn[m]), __fmul_rn(2.0f, dot));
            if (d < d0) { d2 = d1; i2 = i1; d1 = d0; i1 = i0; d0 = d; i0 = m; }
            else if (d < d1) { d2 = d1; i2 = i1; d1 = d; i1 = m; }
            else if (d < d2) { d2 = d; i2 = m; }
        }

        // merge across warp: 3 rounds of butterfly argmin (tie -> lower index)
        float dd[3]; int ii[3];
        #pragma unroll
        for (int r = 0; r < 3; r++) {
            float bd = d0; int bi = i0;
            #pragma unroll
            for (int off = 16; off > 0; off >>= 1) {
                float od = __shfl_xor_sync(0xFFFFFFFF, bd, off);
                int   oi = __shfl_xor_sync(0xFFFFFFFF, bi, off);
                if (od < bd || (od == bd && oi < bi)) { bd = od; bi = oi; }
            }
            dd[r] = bd; ii[r] = bi;
            if (bi == i0)      { d0 = d1; i0 = i1; d1 = d2; i1 = i2; d2 = FLT_MAX; i2 = -1; }
            else if (bi == i1) { d1 = d2; i1 = i2; d2 = FLT_MAX; i2 = -1; }
            else if (bi == i2) { d2 = FLT_MAX; i2 = -1; }
        }

        // weights: exact IEEE divisions (immune to fast-math)
        float w0 = __fdiv_rn(1.0f, __fadd_rn(dd[0], 1e-8f));
        float w1 = __fdiv_rn(1.0f, __fadd_rn(dd[1], 1e-8f));
        float w2 = __fdiv_rn(1.0f, __fadd_rn(dd[2], 1e-8f));
        float ws = __fadd_rn(__fadd_rn(w0, w1), w2);
        w0 = __fdiv_rn(w0, ws); w1 = __fdiv_rn(w1, ws); w2 = __fdiv_rn(w2, ws);

        // project to pixel: NO-FMA chain (hypothesized XLA elementwise lowering)
        float uz0 = proj_row(K00, K01, K02, px, py, pz);
        float uz1 = proj_row(K10, K11, K12, px, py, pz);
        float uz2 = proj_row(K20, K21, K22, px, py, pz);
        float zden = fmaxf(uz2, 1e-8f);
        float uf = floorf(__fdiv_rn(uz0, zden));
        float vf = floorf(__fdiv_rn(uz1, zden));
        int u = (int)fminf(fmaxf(uf, 0.0f), (float)(WW - 1));
        int v = (int)fminf(fmaxf(vf, 0.0f), (float)(HH - 1));
        int pix = v * WW + u;

        const float* x0 = &g_xt[((size_t)b * MM + ii[0]) * CC];
        const float* x1 = &g_xt[((size_t)b * MM + ii[1]) * CC];
        const float* x2 = &g_xt[((size_t)b * MM + ii[2]) * CC];
        size_t base = ((size_t)b * HWH + pix) * CC;
        #pragma unroll
        for (int c8 = 0; c8 < CC / 32; c8++) {
            int c = c8 * 32 + lane;
            float f = w0 * __ldg(&x0[c]) + w1 * __ldg(&x1[c]) + w2 * __ldg(&x2[c]);
            atomicAdd(&g_feat[base + c], f);
        }
        if (lane == 0) atomicAdd(&g_cnt[(size_t)b * HWH + pix], 1.0f);
    }
}

// ---------------------------------------------------------------------------
// Kernel 3: normalize touched pixels, 4x4 average pool, clear scratch in place
// grid: (quarter[4], oy[56], b[4]); block: 256 threads (one per channel)
// ---------------------------------------------------------------------------
__global__ void __launch_bounds__(256) k_pool_clear(float* __restrict__ out) {
    int q  = blockIdx.x;      // ox quarter: covers ox in [q*14, q*14+14)
    int oy = blockIdx.y;
    int b  = blockIdx.z;
    int u0 = q * (OW / 4) * KPOOL;   // 56 columns of u
    int v0 = oy * KPOOL;             // 4 rows of v
    int tid = threadIdx.x;

    __shared__ float acc[14][CC];   // [local ox][c]  (14KB)
    __shared__ float sinv[224];     // 4 rows x 56 cols

    for (int i = tid; i < 14 * CC; i += 256) ((float*)acc)[i] = 0.0f;
    for (int i = tid; i < 224; i += 256) {
        int dy = i / 56, du = i % 56;
        float c = g_cnt[(size_t)b * HWH + (v0 + dy) * WW + (u0 + du)];
        sinv[i] = (c > 0.0f) ? __fdiv_rn(1.0f, c) : 0.0f;
    }
    __syncthreads();

    for (int i = 0; i < 224; i++) {
        float inv = sinv[i];
        if (inv > 0.0f) {
            int dy = i / 56, du = i % 56;
            size_t pbase = ((size_t)b * HWH + (v0 + dy) * WW + (u0 + du)) * CC;
            float val = g_feat[pbase + tid];
            acc[du >> 2][tid] += val * inv;
            g_feat[pbase + tid] = 0.0f;   // restore scratch invariant
        }
    }
    // clear counts for touched pixels
    for (int i = tid; i < 224; i += 256) {
        if (sinv[i] > 0.0f) {
            int dy = i / 56, du = i % 56;
            g_cnt[(size_t)b * HWH + (v0 + dy) * WW + (u0 + du)] = 0.0f;
        }
    }
    __syncthreads();

    // write out[b][c][oy][q*14 + ox]
    for (int i = tid; i < 14 * CC; i += 256) {
        int c = i / 14, ox = i % 14;
        out[(((size_t)b * CC + c) * OH + oy) * OW + q * 14 + ox] = acc[ox][c] * (1.0f / 16.0f);
    }
}

// ---------------------------------------------------------------------------
extern "C" void kernel_launch(void* const* d_in, const int* in_sizes, int n_in,
                              void* d_out, int out_size) {
    const float* feats = (const float*)d_in[0];  // [B][C][M]
    const float* pts   = (const float*)d_in[1];  // [B][N][3]
    const float* ctr   = (const float*)d_in[2];  // [B][M][3]
    const float* Km    = (const float*)d_in[3];  // [3][3]
    float* out = (float*)d_out;

    dim3 tgrid(MM / 32, CC / 32, BB);
    k_transpose<<<tgrid, dim3(32, 8)>>>(feats);

    k_knn_scatter<<<dim3(128, BB), 256>>>(pts, ctr, Km);

    k_pool_clear<<<dim3(4, OH, BB), 256>>>(out);
}

// round 4
// speedup vs baseline: 3.1290x; 3.1290x over previous
#include <cuda_runtime.h>
#include <math.h>
#include <float.h>

// Problem constants (fixed by setup_inputs)
#define BB 4
#define CC 256
#define MM 1024
#define NN 16384
#define HH 224
#define WW 224
#define HWH (HH*WW)
#define KPOOL 4
#define OH (HH/KPOOL)   // 56
#define OW (WW/KPOOL)   // 56
#define PP (OH*OW)      // 3136 pool cells

// Scratch (zero-initialized at module load; every launch restores zeros)
__device__ float g_xt[(size_t)BB * MM * CC];    // xyz_feats transposed: [b][m][c] (4MB)
__device__ float g_pool[(size_t)BB * PP * CC];  // pooled accumulator [b][cell][c] (12.8MB, L2-resident)
__device__ float g_cnt[(size_t)BB * HWH];       // per-pixel point count (800KB)

// ---------------------------------------------------------------------------
// Bit-exact helpers (DO NOT TOUCH — these fix the discrete selection/binning)
// ---------------------------------------------------------------------------
__device__ __forceinline__ float norm3_ref(float x, float y, float z) {
    return __fadd_rn(__fadd_rn(__fmul_rn(x, x), __fmul_rn(y, y)), __fmul_rn(z, z));
}
// Projection row: NO-FMA ascending chain (matches XLA elementwise lowering)
__device__ __forceinline__ float proj_row(float k0, float k1, float k2,
                                          float x, float y, float z) {
    return __fadd_rn(__fadd_rn(__fmul_rn(k0, x), __fmul_rn(k1, y)), __fmul_rn(k2, z));
}
// Pixel index for a point (must be bit-identical between k_count and k_knn_scatter)
__device__ __forceinline__ int pixel_of(const float* __restrict__ Km,
                                        float px, float py, float pz) {
    float uz0 = proj_row(Km[0], Km[1], Km[2], px, py, pz);
    float uz1 = proj_row(Km[3], Km[4], Km[5], px, py, pz);
    float uz2 = proj_row(Km[6], Km[7], Km[8], px, py, pz);
    float zden = fmaxf(uz2, 1e-8f);
    float uf = floorf(__fdiv_rn(uz0, zden));
    float vf = floorf(__fdiv_rn(uz1, zden));
    int u = (int)fminf(fmaxf(uf, 0.0f), (float)(WW - 1));
    int v = (int)fminf(fmaxf(vf, 0.0f), (float)(HH - 1));
    return v * WW + u;
}

// Vector reduction: 4 floats in one instruction (sm_90+)
__device__ __forceinline__ void red_add_v4(float* addr, float4 v) {
    asm volatile("red.global.add.v4.f32 [%0], {%1, %2, %3, %4};"
                 :: "l"(addr), "f"(v.x), "f"(v.y), "f"(v.z), "f"(v.w)
                 : "memory");
}

// ---------------------------------------------------------------------------
// Kernel 1: transpose xyz_feats [B][C][M] -> g_xt [B][M][C]
// ---------------------------------------------------------------------------
__global__ void k_transpose(const float* __restrict__ X) {
    __shared__ float tile[32][33];
    int b  = blockIdx.z;
    int m0 = blockIdx.x * 32;
    int c0 = blockIdx.y * 32;
    int tx = threadIdx.x, ty = threadIdx.y;  // block (32,8)
    #pragma unroll
    for (int k = 0; k < 32; k += 8)
        tile[ty + k][tx] = X[((size_t)b * CC + (c0 + ty + k)) * MM + (m0 + tx)];
    __syncthreads();
    #pragma unroll
    for (int k = 0; k < 32; k += 8)
        g_xt[((size_t)b * MM + (m0 + ty + k)) * CC + (c0 + tx)] = tile[tx][ty + k];
}

// ---------------------------------------------------------------------------
// Kernel 2: per-pixel point counts (tiny)
// ---------------------------------------------------------------------------
__global__ void __launch_bounds__(256) k_count(
    const float* __restrict__ pts, const float* __restrict__ Km)
{
    int b = blockIdx.y;
    int n = blockIdx.x * 256 + threadIdx.x;
    const float* p = &pts[((size_t)b * NN + n) * 3];
    int pix = pixel_of(Km, p[0], p[1], p[2]);
    atomicAdd(&g_cnt[(size_t)b * HWH + pix], 1.0f);
}

// ---------------------------------------------------------------------------
// Kernel 3: thread-per-point 3-NN, then warp-cooperative gather + v4 scatter
// into the L2-resident pooled accumulator.
// ---------------------------------------------------------------------------
__global__ void __launch_bounds__(256) k_knn_scatter(
    const float* __restrict__ pts,   // [B][N][3]
    const float* __restrict__ ctr,   // [B][M][3]
    const float* __restrict__ Km)    // [3][3]
{
    __shared__ float4 sc[MM];        // centers (x,y,z,|c|^2)  16KB
    __shared__ int4   stg_i[256];    // (i0,i1,i2,dstCellBase) 4KB
    __shared__ float4 stg_w[256];    // (w0s,w1s,w2s,-)        4KB

    int b   = blockIdx.y;
    int tid = threadIdx.x;
    int lane = tid & 31;

    for (int i = tid; i < MM; i += 256) {
        float x = ctr[((size_t)b * MM + i) * 3 + 0];
        float y = ctr[((size_t)b * MM + i) * 3 + 1];
        float z = ctr[((size_t)b * MM + i) * 3 + 2];
        sc[i] = make_float4(x, y, z, norm3_ref(x, y, z));
    }
    __syncthreads();

    int n = blockIdx.x * 256 + tid;   // grid.x = NN/256 -> exact, no bounds
    const float* p = &pts[((size_t)b * NN + n) * 3];
    float px = p[0], py = p[1], pz = p[2];
    float pn = norm3_ref(px, py, pz);

    // ---- per-thread top-3, strict-<, ascending m (ties -> earliest index) ----
    float d0 = FLT_MAX, d1 = FLT_MAX, d2 = FLT_MAX;
    int   i0 = 0, i1 = 0, i2 = 0;
    #pragma unroll 4
    for (int m = 0; m < MM; m++) {
        float4 c = sc[m];   // broadcast LDS.128
        float dot = fmaf(pz, c.z, fmaf(py, c.y, __fmul_rn(px, c.x)));
        float d = __fsub_rn(__fadd_rn(pn, c.w), __fmul_rn(2.0f, dot));
        if (d < d2) {
            if (d < d1) {
                d2 = d1; i2 = i1;
                if (d < d0) { d1 = d0; i1 = i0; d0 = d; i0 = m; }
                else        { d1 = d;  i1 = m; }
            } else { d2 = d; i2 = m; }
        }
    }

    // ---- weights (exact IEEE divisions) ----
    float w0 = __fdiv_rn(1.0f, __fadd_rn(d0, 1e-8f));
    float w1 = __fdiv_rn(1.0f, __fadd_rn(d1, 1e-8f));
    float w2 = __fdiv_rn(1.0f, __fadd_rn(d2, 1e-8f));
    float ws = __fadd_rn(__fadd_rn(w0, w1), w2);
    w0 = __fdiv_rn(w0, ws); w1 = __fdiv_rn(w1, ws); w2 = __fdiv_rn(w2, ws);

    // ---- pixel + per-point scale = (1/count) * (1/16) ----
    int pix = pixel_of(Km, px, py, pz);
    float cnt = g_cnt[(size_t)b * HWH + pix];
    float scale = __fdiv_rn(1.0f, cnt) * 0.0625f;   // *1/16 exact
    int v = pix / WW, u = pix % WW;
    int cell = (v >> 2) * OW + (u >> 2);
    int dstBase = (b * PP + cell) * CC;             // float offset into g_pool

    stg_i[tid] = make_int4(i0, i1, i2, dstBase);
    stg_w[tid] = make_float4(w0 * scale, w1 * scale, w2 * scale, 0.0f);
    __syncwarp();

    // ---- warp-cooperative gather + vector scatter ----
    const float4* xt4 = reinterpret_cast<const float4*>(g_xt);
    int wbase = tid & ~31;
    #pragma unroll 1
    for (int k = 0; k < 32; k++) {
        int4   si = stg_i[wbase + k];   // broadcast
        float4 sw = stg_w[wbase + k];
        const float4* r0 = xt4 + ((size_t)b * MM + si.x) * (CC / 4);
        const float4* r1 = xt4 + ((size_t)b * MM + si.y) * (CC / 4);
        const float4* r2 = xt4 + ((size_t)b * MM + si.z) * (CC / 4);
        float* dp = &g_pool[si.w];
        #pragma unroll
        for (int j = 0; j < 2; j++) {
            int c4 = j * 32 + lane;     // float4 index, 64 per row
            float4 a = __ldg(&r0[c4]);
            float4 bq = __ldg(&r1[c4]);
            float4 cq = __ldg(&r2[c4]);
            float4 f;
            f.x = fmaf(sw.x, a.x, fmaf(sw.y, bq.x, sw.z * cq.x));
            f.y = fmaf(sw.x, a.y, fmaf(sw.y, bq.y, sw.z * cq.y));
            f.z = fmaf(sw.x, a.z, fmaf(sw.y, bq.z, sw.z * cq.z));
            f.w = fmaf(sw.x, a.w, fmaf(sw.y, bq.w, sw.z * cq.w));
            red_add_v4(dp + c4 * 4, f);
        }
    }
}

// ---------------------------------------------------------------------------
// Kernel 4: transpose g_pool [b][p][c] -> out [b][c][p], clear scratch.
// grid (PP/32=98, CC/32=8, BB); block (32,8)
// ---------------------------------------------------------------------------
__global__ void k_pool_out(float* __restrict__ out) {
    __shared__ float tile[32][33];
    int b  = blockIdx.z;
    int p0 = blockIdx.x * 32;
    int c0 = blockIdx.y * 32;
    int tx = threadIdx.x, ty = threadIdx.y;
    #pragma unroll
    for (int k = 0; k < 32; k += 8) {
        size_t idx = ((size_t)b * PP + (p0 + ty + k)) * CC + (c0 + tx);
        tile[ty + k][tx] = g_pool[idx];
        g_pool[idx] = 0.0f;                       // restore scratch invariant
    }
    __syncthreads();
    #pragma unroll
    for (int k = 0; k < 32; k += 8)
        out[((size_t)b * CC + (c0 + ty + k)) * PP + (p0 + tx)] = tile[tx][ty + k];
    // clear per-pixel counts (spread across the blockIdx.y==0 slice)
    if (blockIdx.y == 0) {
        int blk = blockIdx.x;                     // 0..97
        int t = ty * 32 + tx;                     // 0..255
        for (int i = blk * 256 + t; i < HWH; i += 98 * 256)
            g_cnt[(size_t)b * HWH + i] = 0.0f;
    }
}

// ---------------------------------------------------------------------------
extern "C" void kernel_launch(void* const* d_in, const int* in_sizes, int n_in,
                              void* d_out, int out_size) {
    const float* feats = (const float*)d_in[0];  // [B][C][M]
    const float* pts   = (const float*)d_in[1];  // [B][N][3]
    const float* ctr   = (const float*)d_in[2];  // [B][M][3]
    const float* Km    = (const float*)d_in[3];  // [3][3]
    float* out = (float*)d_out;

    k_transpose<<<dim3(MM / 32, CC / 32, BB), dim3(32, 8)>>>(feats);
    k_count<<<dim3(NN / 256, BB), 256>>>(pts, Km);
    k_knn_scatter<<<dim3(NN / 256, BB), 256>>>(pts, ctr, Km);
    k_pool_out<<<dim3(PP / 32, CC / 32, BB), dim3(32, 8)>>>(out);
}

// round 5
// speedup vs baseline: 3.6647x; 1.1712x over previous
#include <cuda_runtime.h>
#include <math.h>
#include <float.h>

// Problem constants (fixed by setup_inputs)
#define BB 4
#define CC 256
#define MM 1024
#define NN 16384
#define HH 224
#define WW 224
#define HWH (HH*WW)
#define KPOOL 4
#define OH (HH/KPOOL)   // 56
#define OW (WW/KPOOL)   // 56
#define PP (OH*OW)      // 3136 pool cells

// Scratch (zero-initialized at module load; every launch restores zeros)
__device__ float g_xt[(size_t)BB * MM * CC];    // xyz_feats transposed: [b][m][c] (4MB)
__device__ float g_pool[(size_t)BB * PP * CC];  // pooled accumulator [b][cell][c] (12.8MB)
__device__ float g_cnt[(size_t)BB * HWH];       // per-pixel point count (800KB)

// ---------------------------------------------------------------------------
// Bit-exact helpers (DO NOT TOUCH — these fix the discrete selection/binning)
// ---------------------------------------------------------------------------
__device__ __forceinline__ float norm3_ref(float x, float y, float z) {
    return __fadd_rn(__fadd_rn(__fmul_rn(x, x), __fmul_rn(y, y)), __fmul_rn(z, z));
}
// Projection row: NO-FMA ascending chain (matches XLA elementwise lowering)
__device__ __forceinline__ float proj_row(float k0, float k1, float k2,
                                          float x, float y, float z) {
    return __fadd_rn(__fadd_rn(__fmul_rn(k0, x), __fmul_rn(k1, y)), __fmul_rn(k2, z));
}
__device__ __forceinline__ int pixel_of(const float* __restrict__ Km,
                                        float px, float py, float pz) {
    float uz0 = proj_row(Km[0], Km[1], Km[2], px, py, pz);
    float uz1 = proj_row(Km[3], Km[4], Km[5], px, py, pz);
    float uz2 = proj_row(Km[6], Km[7], Km[8], px, py, pz);
    float zden = fmaxf(uz2, 1e-8f);
    float uf = floorf(__fdiv_rn(uz0, zden));
    float vf = floorf(__fdiv_rn(uz1, zden));
    int u = (int)fminf(fmaxf(uf, 0.0f), (float)(WW - 1));
    int v = (int)fminf(fmaxf(vf, 0.0f), (float)(HH - 1));
    return v * WW + u;
}
// Exact distance recipe (bit-matches reference GEMM + add/sub path)
__device__ __forceinline__ float dist_exact(float px, float py, float pz, float pn,
                                            float4 c) {
    float dot = fmaf(pz, c.z, fmaf(py, c.y, __fmul_rn(px, c.x)));
    return __fsub_rn(__fadd_rn(pn, c.w), __fmul_rn(2.0f, dot));
}

// Vector reduction: 4 floats in one instruction (sm_90+)
__device__ __forceinline__ void red_add_v4(float* addr, float4 v) {
    asm volatile("red.global.add.v4.f32 [%0], {%1, %2, %3, %4};"
                 :: "l"(addr), "f"(v.x), "f"(v.y), "f"(v.z), "f"(v.w)
                 : "memory");
}

// ---------------------------------------------------------------------------
// Kernel 1: transpose xyz_feats [B][C][M] -> g_xt [B][M][C]
// ---------------------------------------------------------------------------
__global__ void k_transpose(const float* __restrict__ X) {
    __shared__ float tile[32][33];
    int b  = blockIdx.z;
    int m0 = blockIdx.x * 32;
    int c0 = blockIdx.y * 32;
    int tx = threadIdx.x, ty = threadIdx.y;  // block (32,8)
    #pragma unroll
    for (int k = 0; k < 32; k += 8)
        tile[ty + k][tx] = X[((size_t)b * CC + (c0 + ty + k)) * MM + (m0 + tx)];
    __syncthreads();
    #pragma unroll
    for (int k = 0; k < 32; k += 8)
        g_xt[((size_t)b * MM + (m0 + ty + k)) * CC + (c0 + tx)] = tile[tx][ty + k];
}

// ---------------------------------------------------------------------------
// Kernel 2: per-pixel point counts (tiny)
// ---------------------------------------------------------------------------
__global__ void __launch_bounds__(256) k_count(
    const float* __restrict__ pts, const float* __restrict__ Km)
{
    int b = blockIdx.y;
    int n = blockIdx.x * 256 + threadIdx.x;
    const float* p = &pts[((size_t)b * NN + n) * 3];
    int pix = pixel_of(Km, p[0], p[1], p[2]);
    atomicAdd(&g_cnt[(size_t)b * HWH + pix], 1.0f);
}

// ---------------------------------------------------------------------------
// Kernel 3: thread-per-point 3-NN (approx-reject fast path), then
// warp-cooperative gather + v4 scatter into pooled accumulator.
// ---------------------------------------------------------------------------
__global__ void __launch_bounds__(256) k_knn_scatter(
    const float* __restrict__ pts,   // [B][N][3]
    const float* __restrict__ ctr,   // [B][M][3]
    const float* __restrict__ Km)    // [3][3]
{
    __shared__ float4 sc[MM];        // centers (x,y,z,|c|^2)  16KB
    __shared__ int4   stg_i[256];    // (i0,i1,i2,dstCellBase) 4KB
    __shared__ float4 stg_w[256];    // (w0s,w1s,w2s,-)        4KB

    int b   = blockIdx.y;
    int tid = threadIdx.x;
    int lane = tid & 31;

    for (int i = tid; i < MM; i += 256) {
        float x = ctr[((size_t)b * MM + i) * 3 + 0];
        float y = ctr[((size_t)b * MM + i) * 3 + 1];
        float z = ctr[((size_t)b * MM + i) * 3 + 2];
        sc[i] = make_float4(x, y, z, norm3_ref(x, y, z));
    }
    __syncthreads();

    int n = blockIdx.x * 256 + tid;
    const float* p = &pts[((size_t)b * NN + n) * 3];
    float px = p[0], py = p[1], pz = p[2];
    float pn = norm3_ref(px, py, pz);
    float npx = -2.0f * px, npy = -2.0f * py, npz = -2.0f * pz;

    // ---- top-3 with approximate rejection (exact insertion on candidates) ----
    float d0 = FLT_MAX, d1 = FLT_MAX, d2 = FLT_MAX;
    int   i0 = 0, i1 = 0, i2 = 0;
    #pragma unroll 1
    for (int mg = 0; mg < MM; mg += 4) {
        // cheap approximate distances (fma chain; error <= ~2e-6 abs)
        float4 c0q = sc[mg + 0], c1q = sc[mg + 1], c2q = sc[mg + 2], c3q = sc[mg + 3];
        float a0 = fmaf(npz, c0q.z, fmaf(npy, c0q.y, fmaf(npx, c0q.x, pn + c0q.w)));
        float a1 = fmaf(npz, c1q.z, fmaf(npy, c1q.y, fmaf(npx, c1q.x, pn + c1q.w)));
        float a2 = fmaf(npz, c2q.z, fmaf(npy, c2q.y, fmaf(npx, c2q.x, pn + c2q.w)));
        float a3 = fmaf(npz, c3q.z, fmaf(npy, c3q.y, fmaf(npx, c3q.x, pn + c3q.w)));
        float mmin = fminf(fminf(a0, a1), fminf(a2, a3));
        if (mmin < d2 + 1e-4f) {
            // exact path: recompute with the bit-exact recipe, ascending m
            #pragma unroll
            for (int t = 0; t < 4; t++) {
                float4 cq = (t == 0) ? c0q : (t == 1) ? c1q : (t == 2) ? c2q : c3q;
                float d = dist_exact(px, py, pz, pn, cq);
                int m = mg + t;
                if (d < d2) {
                    if (d < d1) {
                        d2 = d1; i2 = i1;
                        if (d < d0) { d1 = d0; i1 = i0; d0 = d; i0 = m; }
                        else        { d1 = d;  i1 = m; }
                    } else { d2 = d; i2 = m; }
                }
            }
        }
    }

    // ---- weights (exact IEEE divisions) ----
    float w0 = __fdiv_rn(1.0f, __fadd_rn(d0, 1e-8f));
    float w1 = __fdiv_rn(1.0f, __fadd_rn(d1, 1e-8f));
    float w2 = __fdiv_rn(1.0f, __fadd_rn(d2, 1e-8f));
    float ws = __fadd_rn(__fadd_rn(w0, w1), w2);
    w0 = __fdiv_rn(w0, ws); w1 = __fdiv_rn(w1, ws); w2 = __fdiv_rn(w2, ws);

    // ---- pixel + per-point scale = (1/count) * (1/16) ----
    int pix = pixel_of(Km, px, py, pz);
    float cnt = g_cnt[(size_t)b * HWH + pix];
    float scale = __fdiv_rn(1.0f, cnt) * 0.0625f;
    int v = pix / WW, u = pix % WW;
    int cell = (v >> 2) * OW + (u >> 2);
    int dstBase = (b * PP + cell) * CC;

    stg_i[tid] = make_int4(i0, i1, i2, dstBase);
    stg_w[tid] = make_float4(w0 * scale, w1 * scale, w2 * scale, 0.0f);
    __syncwarp();

    // ---- warp-cooperative gather + vector scatter ----
    const float4* xt4 = reinterpret_cast<const float4*>(g_xt);
    int wbase = tid & ~31;
    #pragma unroll 1
    for (int k = 0; k < 32; k++) {
        int4   si = stg_i[wbase + k];   // broadcast
        float4 sw = stg_w[wbase + k];
        const float4* r0 = xt4 + ((size_t)b * MM + si.x) * (CC / 4);
        const float4* r1 = xt4 + ((size_t)b * MM + si.y) * (CC / 4);
        const float4* r2 = xt4 + ((size_t)b * MM + si.z) * (CC / 4);
        float* dp = &g_pool[si.w];
        #pragma unroll
        for (int j = 0; j < 2; j++) {
            int c4 = j * 32 + lane;
            float4 a  = __ldg(&r0[c4]);
            float4 bq = __ldg(&r1[c4]);
            float4 cq = __ldg(&r2[c4]);
            float4 f;
            f.x = fmaf(sw.x, a.x, fmaf(sw.y, bq.x, sw.z * cq.x));
            f.y = fmaf(sw.x, a.y, fmaf(sw.y, bq.y, sw.z * cq.y));
            f.z = fmaf(sw.x, a.z, fmaf(sw.y, bq.z, sw.z * cq.z));
            f.w = fmaf(sw.x, a.w, fmaf(sw.y, bq.w, sw.z * cq.w));
            red_add_v4(dp + c4 * 4, f);
        }
    }
}

// ---------------------------------------------------------------------------
// Kernel 4: vectorized transpose g_pool [b][p][c] -> out [b][c][p] + clear.
// Tile: 64 cells x 64 channels. grid (49, 4, 4); block 256.
// Per thread: 4x LDG.128 (MLP=4), 4x STG.128 zero, 4x STG.128 out.
// ---------------------------------------------------------------------------
__global__ void __launch_bounds__(256) k_pool_out(float* __restrict__ out) {
    __shared__ float tile[64][65];   // [cell][chan], pitch 65 (2-way conflicts, cheap)
    int b  = blockIdx.z;
    int c0 = blockIdx.y * 64;
    int p0 = blockIdx.x * 64;
    int tid = threadIdx.x;

    float4 v[4];
    #pragma unroll
    for (int r = 0; r < 4; r++) {
        int w = tid + 256 * r;
        int cell = w >> 4, c4 = w & 15;
        size_t idx = ((size_t)b * PP + p0 + cell) * CC + c0 + c4 * 4;
        v[r] = *reinterpret_cast<const float4*>(&g_pool[idx]);
    }
    const float4 z4 = make_float4(0.f, 0.f, 0.f, 0.f);
    #pragma unroll
    for (int r = 0; r < 4; r++) {
        int w = tid + 256 * r;
        int cell = w >> 4, c4 = w & 15;
        size_t idx = ((size_t)b * PP + p0 + cell) * CC + c0 + c4 * 4;
        *reinterpret_cast<float4*>(&g_pool[idx]) = z4;   // restore invariant
        tile[cell][c4 * 4 + 0] = v[r].x;
        tile[cell][c4 * 4 + 1] = v[r].y;
        tile[cell][c4 * 4 + 2] = v[r].z;
        tile[cell][c4 * 4 + 3] = v[r].w;
    }
    // clear per-pixel counts from the y==0 slice (196 blocks x 256 x 4 iters)
    if (blockIdx.y == 0) {
        #pragma unroll
        for (int k = 0; k < 4; k++) {
            int i = blockIdx.x * 256 + tid + k * (49 * 256);
            g_cnt[(size_t)b * HWH + i] = 0.0f;   // 49*256*4 = 50176 = HWH exactly
        }
    }
    __syncthreads();

    #pragma unroll
    for (int r = 0; r < 4; r++) {
        int w = tid + 256 * r;
        int c = w >> 4, p4 = w & 15;
        float4 f;
        f.x = tile[p4 * 4 + 0][c];
        f.y = tile[p4 * 4 + 1][c];
        f.z = tile[p4 * 4 + 2][c];
        f.w = tile[p4 * 4 + 3][c];
        *reinterpret_cast<float4*>(&out[((size_t)b * CC + c0 + c) * PP + p0 + p4 * 4]) = f;
    }
}

// ---------------------------------------------------------------------------
extern "C" void kernel_launch(void* const* d_in, const int* in_sizes, int n_in,
                              void* d_out, int out_size) {
    const float* feats = (const float*)d_in[0];  // [B][C][M]
    const float* pts   = (const float*)d_in[1];  // [B][N][3]
    const float* ctr   = (const float*)d_in[2];  // [B][M][3]
    const float* Km    = (const float*)d_in[3];  // [3][3]
    float* out = (float*)d_out;

    k_transpose<<<dim3(MM / 32, CC / 32, BB), dim3(32, 8)>>>(feats);
    k_count<<<dim3(NN / 256, BB), 256>>>(pts, Km);
    k_knn_scatter<<<dim3(NN / 256, BB), 256>>>(pts, ctr, Km);
    k_pool_out<<<dim3(PP / 64, CC / 64, BB), 256>>>(out);
}